// round 16
// baseline (speedup 1.0000x reference)
#include <cuda_runtime.h>
#include <cuda_fp16.h>
#include <cstdint>
#include <cstring>

#define Bsz 32
#define Ssz 4096
#define Dsz 1280
#define Rsz 64

// fp16 scratch: concatenated pre-rounded params + intermediate H
__device__ __half g_Acat[8 * 128 * Dsz];          // [e][n(128)][k(1280)]
__device__ __half g_Bcat[8 * Dsz * 128];          // [e][d(1280)][k(128)], pre-scaled by ALPHA
__device__ __half g_H[31u * Ssz * 128];           // [b][m][k(128)]

#define XSTG 36864          // 128 rows x 288B (64 fp32 + 8 pad words)
#define ASTG 18432          // 128 rows x 144B (64 halves + pad)
#define STGH 34816          // 128 rows x 272B (128 halves + pad)
#define SMEM1 (2 * XSTG + 2 * ASTG)    // 110592
#define SMEM2 (STGH + 2 * STGH)        // 104448

// ---------------------------------------------------------------------------
__device__ __forceinline__ uint32_t smem_u32(const void* p) {
    uint32_t a;
    asm("{ .reg .u64 t; cvta.to.shared.u64 t, %1; cvt.u32.u64 %0, t; }" : "=r"(a) : "l"(p));
    return a;
}
__device__ __forceinline__ unsigned h2u(__half2 h) {
    unsigned u; memcpy(&u, &h, 4); return u;
}
__device__ __forceinline__ void cp16(uint32_t dst, const void* src) {
    asm volatile("cp.async.cg.shared.global [%0], [%1], 16;" :: "r"(dst), "l"(src));
}
__device__ __forceinline__ void commit_group() {
    asm volatile("cp.async.commit_group;" ::: "memory");
}
__device__ __forceinline__ float2 lds64(uint32_t a) {
    float2 v;
    asm("ld.shared.v2.f32 {%0,%1}, [%2];" : "=f"(v.x), "=f"(v.y) : "r"(a));
    return v;
}
__device__ __forceinline__ void ldsm_x4(unsigned r[4], uint32_t addr) {
    asm volatile("ldmatrix.sync.aligned.m8n8.x4.shared.b16 {%0,%1,%2,%3}, [%4];"
                 : "=r"(r[0]), "=r"(r[1]), "=r"(r[2]), "=r"(r[3]) : "r"(addr));
}
__device__ __forceinline__ void mma16816(float c[4], const unsigned a[4], unsigned b0, unsigned b1) {
    asm volatile(
        "mma.sync.aligned.m16n8k16.row.col.f32.f16.f16.f32 "
        "{%0,%1,%2,%3}, {%4,%5,%6,%7}, {%8,%9}, {%0,%1,%2,%3};"
        : "+f"(c[0]), "+f"(c[1]), "+f"(c[2]), "+f"(c[3])
        : "r"(a[0]), "r"(a[1]), "r"(a[2]), "r"(a[3]), "r"(b0), "r"(b1));
}

// ---------------------------------------------------------------------------
// Pre-convert params to fp16 concatenated layouts (rn rounding), x4 vectorized.
// ALPHA=2 folded into Bcat (exact in fp16: exponent shift only).
// ---------------------------------------------------------------------------
__global__ void preconv_kernel(const float* __restrict__ A_exp,
                               const float* __restrict__ B_exp,
                               const float* __restrict__ A_gen,
                               const float* __restrict__ B_gen)
{
    int idx = blockIdx.x * blockDim.x + threadIdx.x;     // 4-half group index
    const int NG = 8 * 128 * Dsz / 4;                    // 327680
    if (idx < NG) {
        int p = idx * 4;
        // ---- Acat ----
        {
            int e = p / (128 * Dsz);
            int r = p % (128 * Dsz);
            int n = r / Dsz, k = r % Dsz;
            const float* s = (n < Rsz)
                ? (A_exp + ((size_t)e * Rsz + n) * Dsz + k)
                : (A_gen + (size_t)(n - Rsz) * Dsz + k);
            float4 v = *(const float4*)s;
            uint2 o;
            o.x = h2u(__floats2half2_rn(v.x, v.y));
            o.y = h2u(__floats2half2_rn(v.z, v.w));
            *reinterpret_cast<uint2*>(&g_Acat[p]) = o;
        }
        // ---- Bcat (x2 folded) ----
        {
            int e2 = p / (Dsz * 128);
            int r2 = p % (Dsz * 128);
            int d = r2 / 128, k2 = r2 % 128;
            const float* s = (k2 < Rsz)
                ? (B_exp + ((size_t)e2 * Dsz + d) * Rsz + k2)
                : (B_gen + (size_t)d * Rsz + (k2 - Rsz));
            float4 v = *(const float4*)s;
            uint2 o;
            o.x = h2u(__floats2half2_rn(2.0f * v.x, 2.0f * v.y));
            o.y = h2u(__floats2half2_rn(2.0f * v.z, 2.0f * v.w));
            *reinterpret_cast<uint2*>(&g_Bcat[p]) = o;
        }
    }
}

// ---------------------------------------------------------------------------
// GEMM1: H[b] (4096x128) = x[b] @ Acat[b]^T  (R13 mainloop + R15 epilogue).
// grid (32, 32): y < 31 => GEMM tile; y == 31 => zero out[31] slice (no dep
// on H: rides free under gemm1's tensor-bound execution).
// ---------------------------------------------------------------------------
__global__ __launch_bounds__(256, 2) void gemm1_fp16(
    const float* __restrict__ x,
    const int*   __restrict__ label,
    float*       __restrict__ out)
{
    extern __shared__ char smem[];
    const int b   = blockIdx.y;
    const int m0  = blockIdx.x * 128;
    const int tid = threadIdx.x;

    if (b == Bsz - 1) {
        // zero the last sample's slice (reference loops range(B-1))
        float* ob = out + ((size_t)b * Ssz + m0) * Dsz;
        float4 z = make_float4(0.f, 0.f, 0.f, 0.f);
#pragma unroll 4
        for (int i = 0; i < 160; i++) {
            int v = tid + i * 256;       // 40960 float4 = 128 rows x 320
            int row = v / 320, c4 = v % 320;
            __stcs((float4*)(ob + (size_t)row * Dsz + c4 * 4), z);
        }
        return;
    }

    const int e = __ldg(&label[b]);
    const int warp = tid >> 5, lane = tid & 31;
    const int wm = warp & 3, wn = warp >> 2;
    const int lg = lane >> 2, lc = lane & 3;

    uint32_t sX = smem_u32(smem);
    uint32_t sA = sX + 2 * XSTG;

    const char* xb = (const char*)(x + ((size_t)b * Ssz + m0) * Dsz);
    const char* Ab = (const char*)g_Acat + (size_t)e * 128 * Dsz * 2;

    uint32_t xoff[2];
#pragma unroll
    for (int i = 0; i < 2; i++)
        xoff[i] = (uint32_t)((wm * 32 + i * 16 + lg) * 288 + lc * 8);

    uint32_t boff[4];
#pragma unroll
    for (int jp = 0; jp < 4; jp++)
        boff[jp] = (uint32_t)((wn * 64 + jp * 16 + (lane & 7) + ((lane >> 4) << 3)) * 144
                              + (((lane >> 3) & 1) << 4));

    auto stage = [&](int j) {
        uint32_t dX = sX + (j & 1) * XSTG;
        uint32_t dA = sA + (j & 1) * ASTG;
#pragma unroll
        for (int i = 0; i < 8; i++) {
            int cid = tid + i * 256;
            int row = cid >> 4, g = cid & 15;
            cp16(dX + row * 288 + g * 16, xb + (size_t)row * (Dsz * 4) + j * 256 + g * 16);
        }
#pragma unroll
        for (int i = 0; i < 4; i++) {
            int cid = tid + i * 256;
            int row = cid >> 3, g = cid & 7;
            cp16(dA + row * 144 + g * 16, Ab + (size_t)row * (Dsz * 2) + j * 128 + g * 16);
        }
        commit_group();
    };

    stage(0);
    stage(1);
    asm volatile("cp.async.wait_group 1;" ::: "memory");
    __syncthreads();

    float acc[2][8][4] = {};

    const int KT = Dsz / 64;    // 20
#pragma unroll 1
    for (int kt = 0; kt < KT; kt++) {
        uint32_t xS = sX + (kt & 1) * XSTG;
        uint32_t aS = sA + (kt & 1) * ASTG;

#pragma unroll
        for (int kk = 0; kk < 4; kk++) {
            unsigned af[2][4], bf[4][4];
#pragma unroll
            for (int i = 0; i < 2; i++) {
                uint32_t base = xS + xoff[i] + kk * 64;
                float2 p0 = lds64(base);
                float2 p1 = lds64(base + 8 * 288);
                float2 p2 = lds64(base + 32);
                float2 p3 = lds64(base + 8 * 288 + 32);
                af[i][0] = h2u(__floats2half2_rn(p0.x, p0.y));
                af[i][1] = h2u(__floats2half2_rn(p1.x, p1.y));
                af[i][2] = h2u(__floats2half2_rn(p2.x, p2.y));
                af[i][3] = h2u(__floats2half2_rn(p3.x, p3.y));
            }
#pragma unroll
            for (int jp = 0; jp < 4; jp++) ldsm_x4(bf[jp], aS + boff[jp] + kk * 32);
#pragma unroll
            for (int i = 0; i < 2; i++)
#pragma unroll
                for (int jp = 0; jp < 4; jp++) {
                    mma16816(acc[i][2*jp],   af[i], bf[jp][0], bf[jp][1]);
                    mma16816(acc[i][2*jp+1], af[i], bf[jp][2], bf[jp][3]);
                }
        }

        __syncthreads();
        if (kt + 2 < KT) stage(kt + 2);
        else             commit_group();
        asm volatile("cp.async.wait_group 1;" ::: "memory");
        __syncthreads();
    }

    // epilogue: H (fp16) -> global, shfl-merged to STG.64
    __half* Hb = g_H + ((size_t)b * Ssz + m0) * 128;
    const bool odd = (lc & 1);
#pragma unroll
    for (int i = 0; i < 2; i++) {
        int r = wm * 32 + i * 16 + lg;
#pragma unroll
        for (int jp2 = 0; jp2 < 4; jp2++) {
            int j0 = jp2 * 2, j1 = j0 + 1;
#pragma unroll
            for (int h = 0; h < 2; h++) {
                unsigned a0 = h2u(__floats2half2_rn(acc[i][j0][h*2], acc[i][j0][h*2+1]));
                unsigned a1 = h2u(__floats2half2_rn(acc[i][j1][h*2], acc[i][j1][h*2+1]));
                unsigned send = odd ? a0 : a1;
                unsigned recv = __shfl_xor_sync(0xffffffffu, send, 1);
                uint2 v;
                v.x = odd ? recv : a0;
                v.y = odd ? a1   : recv;
                int row = r + h * 8;
                int c2 = wn * 64 + (j0 + (lc & 1)) * 8 + (lc >> 1) * 4;
                *reinterpret_cast<uint2*>(Hb + (size_t)row * 128 + c2) = v;
            }
        }
    }
}

// ---------------------------------------------------------------------------
// GEMM2: out[b] (4096x1280) = H[b] @ Bcat[b]^T  (ALPHA folded into Bcat).
// grid (32, 2, 31), 256 thr; each CTA does 5 of 10 n-tiles. (b==31 handled
// by gemm1's widened grid.)
// ---------------------------------------------------------------------------
__global__ __launch_bounds__(256, 2) void gemm2_fp16(
    const int* __restrict__ label,
    float*     __restrict__ out)
{
    extern __shared__ char smem[];
    const int b   = blockIdx.z;
    const int ny  = blockIdx.y;
    const int m0  = blockIdx.x * 128;
    const int tid = threadIdx.x;
    const int nt0 = ny * 5;

    float* ob = out + ((size_t)b * Ssz + m0) * Dsz;

    const int e = __ldg(&label[b]);
    const int warp = tid >> 5, lane = tid & 31;
    const int wm = warp & 3, wn = warp >> 2;
    const int lg = lane >> 2, lc = lane & 3;

    uint32_t sH = smem_u32(smem);
    uint32_t sB = sH + STGH;

    uint32_t aoff[2], boff[4];
#pragma unroll
    for (int i = 0; i < 2; i++)
        aoff[i] = (uint32_t)((wm * 32 + i * 16 + (lane & 15)) * 272 + ((lane >> 4) << 4));
#pragma unroll
    for (int jp = 0; jp < 4; jp++)
        boff[jp] = (uint32_t)((wn * 64 + jp * 16 + (lane & 7) + ((lane >> 4) << 3)) * 272
                              + (((lane >> 3) & 1) << 4));

    // H tile load (once)
    {
        const char* base = (const char*)g_H + ((size_t)b * Ssz + m0) * 256;
#pragma unroll
        for (int i = 0; i < 8; i++) {
            int cid = tid + i * 256;
            int row = cid >> 4, g = cid & 15;
            cp16(sH + row * 272 + g * 16, base + (size_t)row * 256 + g * 16);
        }
        commit_group();
    }

    auto cp_B = [&](int nt) {
        uint32_t dst = sB + (nt & 1) * STGH;
        const char* base = (const char*)g_Bcat + ((size_t)e * Dsz + nt * 128) * 256;
#pragma unroll
        for (int i = 0; i < 8; i++) {
            int cid = tid + i * 256;
            int row = cid >> 4, g = cid & 15;
            cp16(dst + row * 272 + g * 16, base + (size_t)row * 256 + g * 16);
        }
        commit_group();
    };

    cp_B(nt0);
    cp_B(nt0 + 1);
    asm volatile("cp.async.wait_group 1;" ::: "memory");   // H + B(nt0) ready
    __syncthreads();

#pragma unroll 1
    for (int t = 0; t < 5; t++) {
        const int nt = nt0 + t;
        float acc[2][8][4] = {};
        uint32_t bS = sB + (nt & 1) * STGH;

#pragma unroll
        for (int kk = 0; kk < 8; kk++) {
            unsigned af[2][4], bf[4][4];
            uint32_t kb = kk * 32;
#pragma unroll
            for (int i = 0; i < 2; i++) ldsm_x4(af[i], sH + aoff[i] + kb);
#pragma unroll
            for (int jp = 0; jp < 4; jp++) ldsm_x4(bf[jp], bS + boff[jp] + kb);
#pragma unroll
            for (int i = 0; i < 2; i++)
#pragma unroll
                for (int jp = 0; jp < 4; jp++) {
                    mma16816(acc[i][2*jp],   af[i], bf[jp][0], bf[jp][1]);
                    mma16816(acc[i][2*jp+1], af[i], bf[jp][2], bf[jp][3]);
                }
        }

        __syncthreads();
        if (t + 2 < 5) cp_B(nt + 2);
        else           commit_group();

        // epilogue: pair j-fragments via shfl, emit float4 (64B/row per instr)
        int n0 = nt * 128;
        const bool odd = (lc & 1);
#pragma unroll
        for (int i = 0; i < 2; i++) {
            int r = wm * 32 + i * 16 + lg;
#pragma unroll
            for (int jp2 = 0; jp2 < 4; jp2++) {
                int j0 = jp2 * 2, j1 = j0 + 1;
#pragma unroll
                for (int h = 0; h < 2; h++) {
                    float a0 = acc[i][j0][h*2], a1 = acc[i][j0][h*2+1];
                    float b0 = acc[i][j1][h*2], b1 = acc[i][j1][h*2+1];
                    float s0 = odd ? a0 : b0;
                    float s1 = odd ? a1 : b1;
                    float r0 = __shfl_xor_sync(0xffffffffu, s0, 1);
                    float r1 = __shfl_xor_sync(0xffffffffu, s1, 1);
                    float4 v = odd ? make_float4(r0, r1, b0, b1)
                                   : make_float4(a0, a1, r0, r1);
                    int row = r + h * 8;
                    int c = n0 + wn * 64 + (j0 + (lc & 1)) * 8 + (lc >> 1) * 4;
                    __stcs((float4*)&ob[(size_t)row * Dsz + c], v);
                }
            }
        }

        asm volatile("cp.async.wait_group 1;" ::: "memory");   // B(nt+1) complete
        __syncthreads();
    }
}

// ---------------------------------------------------------------------------
extern "C" void kernel_launch(void* const* d_in, const int* in_sizes, int n_in,
                              void* d_out, int out_size)
{
    const float* x     = (const float*)d_in[0];
    // d_in[1] = weight : unused by the reference
    const float* A_exp = (const float*)d_in[2];
    const float* B_exp = (const float*)d_in[3];
    const float* A_gen = (const float*)d_in[4];
    const float* B_gen = (const float*)d_in[5];
    const int*   label = (const int*)d_in[6];
    float* out = (float*)d_out;

    cudaFuncSetAttribute(gemm1_fp16, cudaFuncAttributeMaxDynamicSharedMemorySize, SMEM1);
    cudaFuncSetAttribute(gemm2_fp16, cudaFuncAttributeMaxDynamicSharedMemorySize, SMEM2);

    preconv_kernel<<<(8 * 128 * Dsz / 4 + 255) / 256, 256>>>(A_exp, B_exp, A_gen, B_gen);
    gemm1_fp16<<<dim3(Ssz / 128, Bsz), 256, SMEM1>>>(x, label, out);
    gemm2_fp16<<<dim3(Ssz / 128, 2, Bsz - 1), 256, SMEM2>>>(label, out);
}

// round 17
// speedup vs baseline: 1.0070x; 1.0070x over previous
#include <cuda_runtime.h>
#include <cuda_fp16.h>
#include <cstdint>
#include <cstring>

#define Bsz 32
#define Ssz 4096
#define Dsz 1280
#define Rsz 64

// fp16 scratch: concatenated pre-rounded params + intermediate H
__device__ __half g_Acat[8 * 128 * Dsz];          // [e][n(128)][k(1280)]
__device__ __half g_Bcat[8 * Dsz * 128];          // [e][d(1280)][k(128)], pre-scaled by ALPHA
__device__ __half g_H[31u * Ssz * 128];           // [b][m][k(128)]

#define XSTG 36864          // 128 rows x 288B (64 fp32 + 8 pad words)
#define ASTG 18432          // 128 rows x 144B (64 halves + pad)
#define STGH 34816          // 128 rows x 272B (128 halves + pad)
#define SMEM1 (2 * XSTG + 2 * ASTG)    // 110592
#define SMEM2 (STGH + 2 * STGH)        // 104448

// ---------------------------------------------------------------------------
__device__ __forceinline__ uint32_t smem_u32(const void* p) {
    uint32_t a;
    asm("{ .reg .u64 t; cvta.to.shared.u64 t, %1; cvt.u32.u64 %0, t; }" : "=r"(a) : "l"(p));
    return a;
}
__device__ __forceinline__ unsigned h2u(__half2 h) {
    unsigned u; memcpy(&u, &h, 4); return u;
}
__device__ __forceinline__ void cp16(uint32_t dst, const void* src) {
    asm volatile("cp.async.cg.shared.global [%0], [%1], 16;" :: "r"(dst), "l"(src));
}
__device__ __forceinline__ void commit_group() {
    asm volatile("cp.async.commit_group;" ::: "memory");
}
__device__ __forceinline__ float2 lds64(uint32_t a) {
    float2 v;
    asm("ld.shared.v2.f32 {%0,%1}, [%2];" : "=f"(v.x), "=f"(v.y) : "r"(a));
    return v;
}
__device__ __forceinline__ void ldsm_x4(unsigned r[4], uint32_t addr) {
    asm volatile("ldmatrix.sync.aligned.m8n8.x4.shared.b16 {%0,%1,%2,%3}, [%4];"
                 : "=r"(r[0]), "=r"(r[1]), "=r"(r[2]), "=r"(r[3]) : "r"(addr));
}
__device__ __forceinline__ void mma16816(float c[4], const unsigned a[4], unsigned b0, unsigned b1) {
    asm volatile(
        "mma.sync.aligned.m16n8k16.row.col.f32.f16.f16.f32 "
        "{%0,%1,%2,%3}, {%4,%5,%6,%7}, {%8,%9}, {%0,%1,%2,%3};"
        : "+f"(c[0]), "+f"(c[1]), "+f"(c[2]), "+f"(c[3])
        : "r"(a[0]), "r"(a[1]), "r"(a[2]), "r"(a[3]), "r"(b0), "r"(b1));
}

// ---------------------------------------------------------------------------
// Pre-convert params to fp16 concatenated layouts (rn rounding), x4 vectorized.
// ALPHA=2 folded into Bcat (exact in fp16: exponent shift only).
// ---------------------------------------------------------------------------
__global__ void preconv_kernel(const float* __restrict__ A_exp,
                               const float* __restrict__ B_exp,
                               const float* __restrict__ A_gen,
                               const float* __restrict__ B_gen)
{
    int idx = blockIdx.x * blockDim.x + threadIdx.x;     // 4-half group index
    const int NG = 8 * 128 * Dsz / 4;                    // 327680
    if (idx < NG) {
        int p = idx * 4;
        // ---- Acat ----
        {
            int e = p / (128 * Dsz);
            int r = p % (128 * Dsz);
            int n = r / Dsz, k = r % Dsz;
            const float* s = (n < Rsz)
                ? (A_exp + ((size_t)e * Rsz + n) * Dsz + k)
                : (A_gen + (size_t)(n - Rsz) * Dsz + k);
            float4 v = *(const float4*)s;
            uint2 o;
            o.x = h2u(__floats2half2_rn(v.x, v.y));
            o.y = h2u(__floats2half2_rn(v.z, v.w));
            *reinterpret_cast<uint2*>(&g_Acat[p]) = o;
        }
        // ---- Bcat (x2 folded) ----
        {
            int e2 = p / (Dsz * 128);
            int r2 = p % (Dsz * 128);
            int d = r2 / 128, k2 = r2 % 128;
            const float* s = (k2 < Rsz)
                ? (B_exp + ((size_t)e2 * Dsz + d) * Rsz + k2)
                : (B_gen + (size_t)d * Rsz + (k2 - Rsz));
            float4 v = *(const float4*)s;
            uint2 o;
            o.x = h2u(__floats2half2_rn(2.0f * v.x, 2.0f * v.y));
            o.y = h2u(__floats2half2_rn(2.0f * v.z, 2.0f * v.w));
            *reinterpret_cast<uint2*>(&g_Bcat[p]) = o;
        }
    }
}

// ---------------------------------------------------------------------------
// GEMM1: H[b] (4096x128) = x[b] @ Acat[b]^T  (R13 mainloop + R15 epilogue).
// grid (32, 31), 256 thr (8 warps 4Mx2N, warp tile 32x64). K-stage 64, KT=20.
// ---------------------------------------------------------------------------
__global__ __launch_bounds__(256, 2) void gemm1_fp16(
    const float* __restrict__ x,
    const int*   __restrict__ label)
{
    extern __shared__ char smem[];
    const int b   = blockIdx.y;
    const int m0  = blockIdx.x * 128;
    const int e   = __ldg(&label[b]);
    const int tid = threadIdx.x;
    const int warp = tid >> 5, lane = tid & 31;
    const int wm = warp & 3, wn = warp >> 2;
    const int lg = lane >> 2, lc = lane & 3;

    uint32_t sX = smem_u32(smem);
    uint32_t sA = sX + 2 * XSTG;

    const char* xb = (const char*)(x + ((size_t)b * Ssz + m0) * Dsz);
    const char* Ab = (const char*)g_Acat + (size_t)e * 128 * Dsz * 2;

    uint32_t xoff[2];
#pragma unroll
    for (int i = 0; i < 2; i++)
        xoff[i] = (uint32_t)((wm * 32 + i * 16 + lg) * 288 + lc * 8);

    uint32_t boff[4];
#pragma unroll
    for (int jp = 0; jp < 4; jp++)
        boff[jp] = (uint32_t)((wn * 64 + jp * 16 + (lane & 7) + ((lane >> 4) << 3)) * 144
                              + (((lane >> 3) & 1) << 4));

    auto stage = [&](int j) {
        uint32_t dX = sX + (j & 1) * XSTG;
        uint32_t dA = sA + (j & 1) * ASTG;
#pragma unroll
        for (int i = 0; i < 8; i++) {
            int cid = tid + i * 256;
            int row = cid >> 4, g = cid & 15;
            cp16(dX + row * 288 + g * 16, xb + (size_t)row * (Dsz * 4) + j * 256 + g * 16);
        }
#pragma unroll
        for (int i = 0; i < 4; i++) {
            int cid = tid + i * 256;
            int row = cid >> 3, g = cid & 7;
            cp16(dA + row * 144 + g * 16, Ab + (size_t)row * (Dsz * 2) + j * 128 + g * 16);
        }
        commit_group();
    };

    stage(0);
    stage(1);
    asm volatile("cp.async.wait_group 1;" ::: "memory");
    __syncthreads();

    float acc[2][8][4] = {};

    const int KT = Dsz / 64;    // 20
#pragma unroll 1
    for (int kt = 0; kt < KT; kt++) {
        uint32_t xS = sX + (kt & 1) * XSTG;
        uint32_t aS = sA + (kt & 1) * ASTG;

#pragma unroll
        for (int kk = 0; kk < 4; kk++) {
            unsigned af[2][4], bf[4][4];
#pragma unroll
            for (int i = 0; i < 2; i++) {
                uint32_t base = xS + xoff[i] + kk * 64;
                float2 p0 = lds64(base);
                float2 p1 = lds64(base + 8 * 288);
                float2 p2 = lds64(base + 32);
                float2 p3 = lds64(base + 8 * 288 + 32);
                af[i][0] = h2u(__floats2half2_rn(p0.x, p0.y));
                af[i][1] = h2u(__floats2half2_rn(p1.x, p1.y));
                af[i][2] = h2u(__floats2half2_rn(p2.x, p2.y));
                af[i][3] = h2u(__floats2half2_rn(p3.x, p3.y));
            }
#pragma unroll
            for (int jp = 0; jp < 4; jp++) ldsm_x4(bf[jp], aS + boff[jp] + kk * 32);
#pragma unroll
            for (int i = 0; i < 2; i++)
#pragma unroll
                for (int jp = 0; jp < 4; jp++) {
                    mma16816(acc[i][2*jp],   af[i], bf[jp][0], bf[jp][1]);
                    mma16816(acc[i][2*jp+1], af[i], bf[jp][2], bf[jp][3]);
                }
        }

        if (kt + 1 < KT) {                        // skip dead sync/wait on final iter
            __syncthreads();
            if (kt + 2 < KT) stage(kt + 2);
            else             commit_group();
            asm volatile("cp.async.wait_group 1;" ::: "memory");
            __syncthreads();
        }
    }

    // epilogue: H (fp16) -> global, shfl-merged to STG.64
    __half* Hb = g_H + ((size_t)b * Ssz + m0) * 128;
    const bool odd = (lc & 1);
#pragma unroll
    for (int i = 0; i < 2; i++) {
        int r = wm * 32 + i * 16 + lg;
#pragma unroll
        for (int jp2 = 0; jp2 < 4; jp2++) {
            int j0 = jp2 * 2, j1 = j0 + 1;
#pragma unroll
            for (int h = 0; h < 2; h++) {
                unsigned a0 = h2u(__floats2half2_rn(acc[i][j0][h*2], acc[i][j0][h*2+1]));
                unsigned a1 = h2u(__floats2half2_rn(acc[i][j1][h*2], acc[i][j1][h*2+1]));
                unsigned send = odd ? a0 : a1;
                unsigned recv = __shfl_xor_sync(0xffffffffu, send, 1);
                uint2 v;
                v.x = odd ? recv : a0;
                v.y = odd ? a1   : recv;
                int row = r + h * 8;
                int c2 = wn * 64 + (j0 + (lc & 1)) * 8 + (lc >> 1) * 4;
                *reinterpret_cast<uint2*>(Hb + (size_t)row * 128 + c2) = v;
            }
        }
    }
}

// ---------------------------------------------------------------------------
// GEMM2: out[b] (4096x1280) = H[b] @ Bcat[b]^T  (ALPHA folded into Bcat).
// grid (32, 2, 32), 256 thr; each CTA does 5 of 10 n-tiles.
// b==31 CTAs zero their half-slice (R15 placement — proven cheapest).
// ---------------------------------------------------------------------------
__global__ __launch_bounds__(256, 2) void gemm2_fp16(
    const int* __restrict__ label,
    float*     __restrict__ out)
{
    extern __shared__ char smem[];
    const int b   = blockIdx.z;
    const int ny  = blockIdx.y;
    const int m0  = blockIdx.x * 128;
    const int tid = threadIdx.x;
    const int nt0 = ny * 5;

    float* ob = out + ((size_t)b * Ssz + m0) * Dsz;

    if (b == Bsz - 1) {
        float4 z = make_float4(0.f, 0.f, 0.f, 0.f);
        float* obh = ob + ny * 640;
#pragma unroll 4
        for (int i = 0; i < 80; i++) {
            int v = tid + i * 256;
            int row = v / 160, c4 = v % 160;
            __stcs((float4*)(obh + (size_t)row * Dsz + c4 * 4), z);
        }
        return;
    }

    const int e = __ldg(&label[b]);
    const int warp = tid >> 5, lane = tid & 31;
    const int wm = warp & 3, wn = warp >> 2;
    const int lg = lane >> 2, lc = lane & 3;

    uint32_t sH = smem_u32(smem);
    uint32_t sB = sH + STGH;

    uint32_t aoff[2], boff[4];
#pragma unroll
    for (int i = 0; i < 2; i++)
        aoff[i] = (uint32_t)((wm * 32 + i * 16 + (lane & 15)) * 272 + ((lane >> 4) << 4));
#pragma unroll
    for (int jp = 0; jp < 4; jp++)
        boff[jp] = (uint32_t)((wn * 64 + jp * 16 + (lane & 7) + ((lane >> 4) << 3)) * 272
                              + (((lane >> 3) & 1) << 4));

    // H tile load (once)
    {
        const char* base = (const char*)g_H + ((size_t)b * Ssz + m0) * 256;
#pragma unroll
        for (int i = 0; i < 8; i++) {
            int cid = tid + i * 256;
            int row = cid >> 4, g = cid & 15;
            cp16(sH + row * 272 + g * 16, base + (size_t)row * 256 + g * 16);
        }
        commit_group();
    }

    auto cp_B = [&](int nt) {
        uint32_t dst = sB + (nt & 1) * STGH;
        const char* base = (const char*)g_Bcat + ((size_t)e * Dsz + nt * 128) * 256;
#pragma unroll
        for (int i = 0; i < 8; i++) {
            int cid = tid + i * 256;
            int row = cid >> 4, g = cid & 15;
            cp16(dst + row * 272 + g * 16, base + (size_t)row * 256 + g * 16);
        }
        commit_group();
    };

    cp_B(nt0);
    cp_B(nt0 + 1);
    asm volatile("cp.async.wait_group 1;" ::: "memory");   // H + B(nt0) ready
    __syncthreads();

#pragma unroll 1
    for (int t = 0; t < 5; t++) {
        const int nt = nt0 + t;
        float acc[2][8][4] = {};
        uint32_t bS = sB + (nt & 1) * STGH;

#pragma unroll
        for (int kk = 0; kk < 8; kk++) {
            unsigned af[2][4], bf[4][4];
            uint32_t kb = kk * 32;
#pragma unroll
            for (int i = 0; i < 2; i++) ldsm_x4(af[i], sH + aoff[i] + kb);
#pragma unroll
            for (int jp = 0; jp < 4; jp++) ldsm_x4(bf[jp], bS + boff[jp] + kb);
#pragma unroll
            for (int i = 0; i < 2; i++)
#pragma unroll
                for (int jp = 0; jp < 4; jp++) {
                    mma16816(acc[i][2*jp],   af[i], bf[jp][0], bf[jp][1]);
                    mma16816(acc[i][2*jp+1], af[i], bf[jp][2], bf[jp][3]);
                }
        }

        if (t + 1 < 5) {
            __syncthreads();                      // warps done reading slot nt&1
            if (t + 2 < 5) cp_B(nt + 2);          // refill freed slot
            else           commit_group();
        }

        // epilogue: pair j-fragments via shfl, emit float4 (64B/row per instr)
        int n0 = nt * 128;
        const bool odd = (lc & 1);
#pragma unroll
        for (int i = 0; i < 2; i++) {
            int r = wm * 32 + i * 16 + lg;
#pragma unroll
            for (int jp2 = 0; jp2 < 4; jp2++) {
                int j0 = jp2 * 2, j1 = j0 + 1;
#pragma unroll
                for (int h = 0; h < 2; h++) {
                    float a0 = acc[i][j0][h*2], a1 = acc[i][j0][h*2+1];
                    float b0 = acc[i][j1][h*2], b1 = acc[i][j1][h*2+1];
                    float s0 = odd ? a0 : b0;
                    float s1 = odd ? a1 : b1;
                    float r0 = __shfl_xor_sync(0xffffffffu, s0, 1);
                    float r1 = __shfl_xor_sync(0xffffffffu, s1, 1);
                    float4 v = odd ? make_float4(r0, r1, b0, b1)
                                   : make_float4(a0, a1, r0, r1);
                    int row = r + h * 8;
                    int c = n0 + wn * 64 + (j0 + (lc & 1)) * 8 + (lc >> 1) * 4;
                    __stcs((float4*)&ob[(size_t)row * Dsz + c], v);
                }
            }
        }

        if (t + 1 < 5) {
            asm volatile("cp.async.wait_group 1;" ::: "memory");   // B(nt+1) done
            __syncthreads();
        }
    }
}

// ---------------------------------------------------------------------------
extern "C" void kernel_launch(void* const* d_in, const int* in_sizes, int n_in,
                              void* d_out, int out_size)
{
    const float* x     = (const float*)d_in[0];
    // d_in[1] = weight : unused by the reference
    const float* A_exp = (const float*)d_in[2];
    const float* B_exp = (const float*)d_in[3];
    const float* A_gen = (const float*)d_in[4];
    const float* B_gen = (const float*)d_in[5];
    const int*   label = (const int*)d_in[6];
    float* out = (float*)d_out;

    cudaFuncSetAttribute(gemm1_fp16, cudaFuncAttributeMaxDynamicSharedMemorySize, SMEM1);
    cudaFuncSetAttribute(gemm2_fp16, cudaFuncAttributeMaxDynamicSharedMemorySize, SMEM2);

    preconv_kernel<<<(8 * 128 * Dsz / 4 + 255) / 256, 256>>>(A_exp, B_exp, A_gen, B_gen);
    gemm1_fp16<<<dim3(Ssz / 128, Bsz - 1), 256, SMEM1>>>(x, label);
    gemm2_fp16<<<dim3(Ssz / 128, 2, Bsz), 256, SMEM2>>>(label, out);
}